// round 17
// baseline (speedup 1.0000x reference)
#include <cuda_runtime.h>
#include <cuda_fp16.h>
#include <math.h>
#include <stdint.h>

// Problem constants
#define BV 512
#define TV 64
#define FV 256
#define HV 1024

#define OFF_REC   (BV*TV*FV)
#define OFF_HFIN  (2*BV*TV*FV)
#define OFF_LOSS  (2*BV*TV*FV + BV*HV)

#define NB2 32   // loss partial tiles per step

// ---------------- scratch ----------------
__device__ float g_h[BV*HV];
__device__ float g_xh[BV*FV];
__device__ float g_gh[BV*3*HV];
__device__ float g_gammaH[(size_t)TV*BV*HV];
__device__ float g_beta[(size_t)TV*BV*FV];
__device__ float g_msum[TV];
__device__ float g_lossPart[TV*NB2];

// ---- pre-swizzled fp16 B (weights); uint2 = one (n8,k16) lane fragment ----
#define SZB(N,K) ((N)*(K)/4)
#define BOFF_G1 0
#define BOFF_G3 (BOFF_G1 + SZB(3328,1024))
#define BOFF_G2 (BOFF_G3 + SZB(3072,512))
#define BOFF_P1 (BOFF_G2 + SZB(256,256))
#define BOFF_P2 (BOFF_P1 + SZB(1024,256))
#define BSWZ_TOTAL (BOFF_P2 + SZB(256,512))
__device__ uint2 g_Bswz[BSWZ_TOTAL];

// ---- pre-swizzled fp16 A (activations); offsets in ELEMENT (halfword) units ----
#define AOFF_G1 0                                   // 512x1024
#define AOFF_G2 (AOFF_G1 + BV*HV)                   // 512x256
#define AOFF_G3 (AOFF_G2 + BV*FV)                   // 64 slices of 512x512
#define AG3_STRIDE (BV*2*FV)
#define AOFF_P1 (AOFF_G3 + TV*AG3_STRIDE)           // 32768x256
#define AOFF_P2 (AOFF_P1 + TV*BV*FV)                // 32768x512
#define ASWZ_TOTAL (AOFF_P2 + TV*BV*2*FV)
__device__ uint4 g_Aswz4[ASWZ_TOTAL/8];
#define ASWZ_H ((uint16_t*)g_Aswz4)
#define ASWZ_W ((uint32_t*)g_Aswz4)

__device__ __forceinline__ uint16_t f2h(float f) {
    return __half_as_ushort(__float2half_rn(f));
}
__device__ __forceinline__ uint32_t pack2h(float a, float b) {
    return (uint32_t)f2h(a) | ((uint32_t)f2h(b) << 16);
}

// PDL primitives (safe no-ops without PDL launch attrs)
__device__ __forceinline__ void gdc_wait() {
    asm volatile("griddepcontrol.wait;" ::: "memory");
}
__device__ __forceinline__ void gdc_launch() {
    asm volatile("griddepcontrol.launch_dependents;");
}

// element index of A(m,k) in fp16 m16n8k16 fragment-native layout (KT16 = K/16)
__device__ __forceinline__ int aidx16(int m, int k, int KT16) {
    int r = m & 15, c = k & 15;
    int lane = (r & 7)*4 + ((c & 7) >> 1);
    int reg  = (r >> 3) + ((c >> 3) << 1);
    return ((((m >> 4)*KT16 + (k >> 4))*32 + lane)*4 + reg)*2 + (c & 1);
}
// element index of B(n,k) in fp16 m16n8k16 fragment-native layout
__device__ __forceinline__ int bidx16(int n, int k, int KT16) {
    int c = k & 15;
    int lane = (n & 7)*4 + ((c & 7) >> 1);
    int reg  = (c >> 3) & 1;
    return ((((n >> 3)*KT16 + (k >> 4))*32 + lane)*2 + reg)*2 + (k & 1);
}

// ---------------- weight pre-swizzle (paired k) ----------------
template<class BL>
__global__ void swz_k(int boff, int N, int K, BL bl) {
    int idx = blockIdx.x * 256 + threadIdx.x;
    if (idx >= N*(K >> 1)) return;
    int n = idx / (K >> 1), k = (idx % (K >> 1)) * 2;
    uint32_t* d = (uint32_t*)(g_Bswz + boff);
    d[bidx16(n, k, K >> 4) >> 1] = pack2h(bl(n, k), bl(n, k + 1));
}

// ------------- fp16 m16n8k16 GEMM: pre-swizzled A via smem, B direct LDG. BK = 64 -------------
template<int BM,int BN,int WM,int WN,class EP>
__global__ __launch_bounds__(256, 2)
void tgemm4_k(int K, int aoff, int boff, EP ep) {
    constexpr int WARPS_M = BM/WM, WARPS_N = BN/WN;
    static_assert(WARPS_M*WARPS_N == 8, "need 8 warps");
    constexpr int MI = WM/16, NI = WN/8;
    constexpr int KT = 4;
    constexpr int TILE4 = (BM/16)*KT*32;
    constexpr int CP = TILE4/256;

    __shared__ uint4 As[2][TILE4];
    __shared__ float red[256];

    const int KT16 = K >> 4;
    const int tid = threadIdx.x, lane = tid & 31, wid = tid >> 5;
    const int wm = (wid % WARPS_M)*WM, wn = (wid / WARPS_M)*WN;
    const int gid = lane >> 2, tig = lane & 3;
    const int bm = blockIdx.y*BM, bn = blockIdx.x*BN;
    const int mtBase = bm >> 4;
    const int ntBase = (bn + wn) >> 3;
    const int wmt = wm >> 4;

    const uint4* __restrict__ Ag = (const uint4*)(ASWZ_H + aoff);
    const uint2* __restrict__ Bg = g_Bswz + boff;

    float acc[MI][NI][4];
    #pragma unroll
    for (int mi = 0; mi < MI; mi++)
        #pragma unroll
        for (int ni = 0; ni < NI; ni++)
            #pragma unroll
            for (int c = 0; c < 4; c++) acc[mi][ni][c] = 0.f;

    uint4 ar[CP];
    auto ldA = [&](int kt0) {
        #pragma unroll
        for (int i = 0; i < CP; i++) {
            int e = tid + i*256;
            int mtl = e / (KT*32), rem = e % (KT*32);
            ar[i] = Ag[((mtBase + mtl)*KT16 + kt0 + rem/32)*32 + (rem & 31)];
        }
    };
    auto stA = [&](int buf) {
        #pragma unroll
        for (int i = 0; i < CP; i++) As[buf][tid + i*256] = ar[i];
    };

    gdc_wait();

    ldA(0); stA(0);
    __syncthreads();

    int cur = 0;
    for (int kt0 = 0; kt0 < KT16; kt0 += KT) {
        const bool more = (kt0 + KT) < KT16;
        uint2 bf[NI][KT];
        #pragma unroll
        for (int ni = 0; ni < NI; ni++)
            #pragma unroll
            for (int kk = 0; kk < KT; kk++)
                bf[ni][kk] = Bg[((ntBase + ni)*KT16 + kt0 + kk)*32 + lane];
        if (more) ldA(kt0 + KT);

        #pragma unroll
        for (int kk = 0; kk < KT; kk++) {
            uint4 av[MI];
            #pragma unroll
            for (int mi = 0; mi < MI; mi++)
                av[mi] = As[cur][((wmt + mi)*KT + kk)*32 + lane];
            #pragma unroll
            for (int mi = 0; mi < MI; mi++)
                #pragma unroll
                for (int ni = 0; ni < NI; ni++)
                    asm volatile(
                        "mma.sync.aligned.m16n8k16.row.col.f32.f16.f16.f32 "
                        "{%0,%1,%2,%3}, {%4,%5,%6,%7}, {%8,%9}, {%0,%1,%2,%3};"
                        : "+f"(acc[mi][ni][0]), "+f"(acc[mi][ni][1]),
                          "+f"(acc[mi][ni][2]), "+f"(acc[mi][ni][3])
                        : "r"(av[mi].x), "r"(av[mi].y), "r"(av[mi].z), "r"(av[mi].w),
                          "r"(bf[ni][kk].x), "r"(bf[ni][kk].y));
        }
        if (more) stA(cur ^ 1);
        __syncthreads();
        cur ^= 1;
    }

    float rsum = 0.f;
    #pragma unroll
    for (int mi = 0; mi < MI; mi++) {
        #pragma unroll
        for (int ni = 0; ni < NI; ni++) {
            int gm0 = bm + wm + mi*16 + gid;
            int gn0 = bn + wn + ni*8 + tig*2;
            rsum += ep(gm0,     gn0,     acc[mi][ni][0]);
            rsum += ep(gm0,     gn0 + 1, acc[mi][ni][1]);
            rsum += ep(gm0 + 8, gn0,     acc[mi][ni][2]);
            rsum += ep(gm0 + 8, gn0 + 1, acc[mi][ni][3]);
        }
    }

    if constexpr (EP::RED) {
        red[tid] = rsum;
        __syncthreads();
        for (int s = 128; s > 0; s >>= 1) {
            if (tid < s) red[tid] += red[tid + s];
            __syncthreads();
        }
        if (tid == 0) {
            int lin = blockIdx.y * gridDim.x + blockIdx.x;
            ep.store_partial(lin, red[0]);
        }
    }
    gdc_launch();
}

// ---------------- fused G3 + GRU kernel ----------------
// gi = [x_imp, m] @ Wih^T + bih with all THREE gates per block, then the full GRU
// update in the epilogue (reads g_gh/g_h/gammaH, writes g_h, hfin, next G1 A image).
// Grid (16, 8): bj = x*64 (hidden j), bm = y*64 (batch). 8 warps: 2 (M) x 4 (J).
__global__ __launch_bounds__(256, 1)
void g3gru_k(int aoff, const float* __restrict__ bih, int t, float* __restrict__ hfin) {
    constexpr int KT = 4;
    constexpr int TILE4 = 4*KT*32;      // (BM/16)*KT*32 = 512
    constexpr int CP = TILE4/256;
    constexpr int KT16 = 32;            // K = 512

    __shared__ uint4 As[2][TILE4];

    const int tid = threadIdx.x, lane = tid & 31, wid = tid >> 5;
    const int wm = (wid & 1)*32;        // WARPS_M = 2, WM = 32 (MI=2)
    const int wj = (wid >> 1)*16;       // WARPS_J = 4, WNJ = 16 (NI=2)
    const int gid = lane >> 2, tig = lane & 3;
    const int bj = blockIdx.x*64, bm = blockIdx.y*64;
    const int mtBase = bm >> 4;
    const int wmt = wm >> 4;

    const uint4* __restrict__ Ag = (const uint4*)(ASWZ_H + aoff);
    const uint2* __restrict__ Bg = g_Bswz + BOFF_G3;
    int ntB[3];
    #pragma unroll
    for (int g = 0; g < 3; g++) ntB[g] = (g*HV + bj + wj) >> 3;

    float acc[3][2][2][4];
    #pragma unroll
    for (int g = 0; g < 3; g++)
        #pragma unroll
        for (int mi = 0; mi < 2; mi++)
            #pragma unroll
            for (int ni = 0; ni < 2; ni++)
                #pragma unroll
                for (int c = 0; c < 4; c++) acc[g][mi][ni][c] = 0.f;

    uint4 ar[CP];
    auto ldA = [&](int kt0) {
        #pragma unroll
        for (int i = 0; i < CP; i++) {
            int e = tid + i*256;
            int mtl = e / (KT*32), rem = e % (KT*32);
            ar[i] = Ag[((mtBase + mtl)*KT16 + kt0 + rem/32)*32 + (rem & 31)];
        }
    };
    auto stA = [&](int buf) {
        #pragma unroll
        for (int i = 0; i < CP; i++) As[buf][tid + i*256] = ar[i];
    };

    gdc_wait();

    ldA(0); stA(0);
    __syncthreads();

    int cur = 0;
    for (int kt0 = 0; kt0 < KT16; kt0 += KT) {
        const bool more = (kt0 + KT) < KT16;
        uint2 bf[3][2][KT];
        #pragma unroll
        for (int g = 0; g < 3; g++)
            #pragma unroll
            for (int ni = 0; ni < 2; ni++)
                #pragma unroll
                for (int kk = 0; kk < KT; kk++)
                    bf[g][ni][kk] = Bg[((ntB[g] + ni)*KT16 + kt0 + kk)*32 + lane];
        if (more) ldA(kt0 + KT);

        #pragma unroll
        for (int kk = 0; kk < KT; kk++) {
            uint4 av[2];
            #pragma unroll
            for (int mi = 0; mi < 2; mi++)
                av[mi] = As[cur][((wmt + mi)*KT + kk)*32 + lane];
            #pragma unroll
            for (int g = 0; g < 3; g++)
                #pragma unroll
                for (int mi = 0; mi < 2; mi++)
                    #pragma unroll
                    for (int ni = 0; ni < 2; ni++)
                        asm volatile(
                            "mma.sync.aligned.m16n8k16.row.col.f32.f16.f16.f32 "
                            "{%0,%1,%2,%3}, {%4,%5,%6,%7}, {%8,%9}, {%0,%1,%2,%3};"
                            : "+f"(acc[g][mi][ni][0]), "+f"(acc[g][mi][ni][1]),
                              "+f"(acc[g][mi][ni][2]), "+f"(acc[g][mi][ni][3])
                            : "r"(av[mi].x), "r"(av[mi].y), "r"(av[mi].z), "r"(av[mi].w),
                              "r"(bf[g][ni][kk].x), "r"(bf[g][ni][kk].y));
        }
        if (more) stA(cur ^ 1);
        __syncthreads();
        cur ^= 1;
    }

    // fused GRU epilogue
    #pragma unroll
    for (int mi = 0; mi < 2; mi++) {
        #pragma unroll
        for (int ni = 0; ni < 2; ni++) {
            int j0 = bj + wj + ni*8 + tig*2;
            #pragma unroll
            for (int rr = 0; rr < 2; rr++) {
                int m = bm + wm + mi*16 + gid + rr*8;
                int ci = rr*2;
                float hn2[2];
                #pragma unroll
                for (int u = 0; u < 2; u++) {
                    int j = j0 + u;
                    int gb = m*3*HV + j;
                    float ir = acc[0][mi][ni][ci+u] + bih[j]        + g_gh[gb];
                    float iz = acc[1][mi][ni][ci+u] + bih[HV + j]   + g_gh[gb + HV];
                    float in2 = acc[2][mi][ni][ci+u] + bih[2*HV + j];
                    float r_ = 1.f / (1.f + expf(-ir));
                    float z_ = 1.f / (1.f + expf(-iz));
                    float n_ = tanhf(in2 + r_ * g_gh[gb + 2*HV]);
                    int e = m*HV + j;
                    float hd = g_h[e] * g_gammaH[(size_t)t*BV*HV + e];
                    float hn = (1.f - z_)*n_ + z_*hd;
                    g_h[e] = hn;
                    if (hfin) hfin[e] = hn;
                    hn2[u] = hn;
                }
                if (t + 1 < TV) {
                    int e0 = m*HV + j0;
                    ASWZ_W[(AOFF_G1 + aidx16(m, j0, 64)) >> 1] =
                        pack2h(hn2[0] * g_gammaH[(size_t)(t+1)*BV*HV + e0],
                               hn2[1] * g_gammaH[(size_t)(t+1)*BV*HV + e0 + 1]);
                }
            }
        }
    }
    gdc_launch();
}

// ---------------- B-side scalar loaders ----------------
struct BL_P1 {
    const float* Wdh;
    __device__ float operator()(int n, int k) const { return Wdh[n*FV + k]; }
};
struct BL_P2 {
    const float* Wwc;
    __device__ float operator()(int n, int k) const { return Wwc[n*(2*FV) + k]; }
};
struct BL_G1 {
    const float* Wh; const float* Whh;
    __device__ float operator()(int n, int k) const {
        return (n < FV) ? Wh[n*HV + k] : Whh[(n - FV)*HV + k];
    }
};
struct BL_G2 {
    const float* Wfr;
    __device__ float operator()(int n, int k) const {
        return (n == k) ? 0.f : Wfr[n*FV + k];
    }
};
struct BL_G3 {
    const float* Wih;
    __device__ float operator()(int n, int k) const { return Wih[n*(2*FV) + k]; }
};

// ---------------- A-side pre-swizzle kernels (paired k) ----------------
__global__ void swzA_P1_k(const float* __restrict__ deltas) {
    int idx = blockIdx.x * 256 + threadIdx.x;
    int m = idx >> 7, k = (idx & 127) * 2;
    int t = m >> 9, b = m & 511;
    const float* src = &deltas[(b*TV + t)*FV + k];
    ASWZ_W[(AOFF_P1 + aidx16(m, k, 16)) >> 1] = pack2h(src[0], src[1]);
}

__global__ void swzA_P2_k(const float* __restrict__ deltas, const float* __restrict__ mask,
                          const float* __restrict__ Wdx, const float* __restrict__ bdx) {
    int idx = blockIdx.x * 256 + threadIdx.x;
    int m = idx >> 8, k = (idx & 255) * 2;
    int t = m >> 9, b = m & 511;
    float v0, v1;
    if (k < FV) {
        float d0 = deltas[(b*TV + t)*FV + k];
        float d1 = deltas[(b*TV + t)*FV + k + 1];
        v0 = expf(-fmaxf(d0 * Wdx[k*FV + k] + bdx[k], 0.f));
        v1 = expf(-fmaxf(d1 * Wdx[(k+1)*FV + (k+1)] + bdx[k+1], 0.f));
    } else {
        v0 = mask[(b*TV + t)*FV + (k - FV)];
        v1 = mask[(b*TV + t)*FV + (k - FV) + 1];
    }
    ASWZ_W[(AOFF_P2 + aidx16(m, k, 32)) >> 1] = pack2h(v0, v1);
}

__global__ void swzA_G3m_k(const float* __restrict__ mask) {
    int idx = blockIdx.x * 256 + threadIdx.x;
    int t = idx >> 16, b = (idx >> 7) & 511, f = (idx & 127) * 2;
    const float* src = &mask[(b*TV + t)*FV + f];
    ASWZ_W[(AOFF_G3 + t*AG3_STRIDE + aidx16(b, FV + f, 32)) >> 1] =
        pack2h(src[0], src[1]);
}

// h init: plain h0 + swizzled fp16 h0*gammaH[0]
__global__ void hAinit_k(const float* __restrict__ h0) {
    int idx = blockIdx.x * 256 + threadIdx.x;
    int b = idx >> 9, j = (idx & 511) * 2;
    int e = b*HV + j;
    float ha = h0[e], hb = h0[e+1];
    g_h[e] = ha; g_h[e+1] = hb;
    ASWZ_W[(AOFF_G1 + aidx16(b, j, 64)) >> 1] =
        pack2h(ha * g_gammaH[e], hb * g_gammaH[e+1]);
}

// ---------------- epilogues ----------------
struct EP_P1 {
    const float* bdh;
    static constexpr bool RED = false;
    __device__ float operator()(int m, int n, float v) const {
        g_gammaH[(size_t)m*HV + n] = expf(-fmaxf(v + bdh[n], 0.f));
        return 0.f;
    }
    __device__ void store_partial(int, float) const {}
};
struct EP_P2 {
    const float* bwc;
    static constexpr bool RED = false;
    __device__ float operator()(int m, int n, float v) const {
        g_beta[(size_t)m*FV + n] = v + bwc[n];
        return 0.f;
    }
    __device__ void store_partial(int, float) const {}
};
struct EP_G1 {
    const float* bh; const float* bhh; const float* x; const float* mask; int t;
    static constexpr bool RED = false;
    __device__ float operator()(int m, int n, float v) const {
        if (n < FV) {
            float xh = v + bh[n];
            g_xh[m*FV + n] = xh;
            int idx = (m*TV + t)*FV + n;
            float mt = mask[idx];
            float xr = mt * x[idx] + (1.f - mt) * xh;
            ASWZ_H[AOFF_G2 + aidx16(m, n, 16)] = f2h(xr);
        } else {
            g_gh[m*3*HV + (n - FV)] = v + bhh[n - FV];
        }
        return 0.f;
    }
    __device__ void store_partial(int, float) const {}
};
struct EP_G2 {
    const float* bfr; const float* x; const float* mask;
    float* rec; float* ximp; int t;
    static constexpr bool RED = true;
    __device__ float operator()(int m, int n, float v) const {
        float xu = v + bfr[n];
        float xh = g_xh[m*FV + n];
        float be = g_beta[(size_t)t*BV*FV + m*FV + n];
        float xc = be * xu + (1.f - be) * xh;
        int idx = (m*TV + t)*FV + n;
        float mt = mask[idx], xt = x[idx];
        rec[idx]  = xc;
        float xi = mt * xt + (1.f - mt) * xc;
        ximp[idx] = xi;
        ASWZ_H[AOFF_G3 + t*AG3_STRIDE + aidx16(m, n, 32)] = f2h(xi);
        return fabsf(xc - xt) * mt;
    }
    __device__ void store_partial(int lin, float v) const {
        g_lossPart[t*NB2 + lin] = v;
    }
};

// ---------------- elementwise kernels ----------------
__global__ void msum_k(const float* __restrict__ mask) {
    int t = blockIdx.x;
    float s = 0.f;
    for (int i = threadIdx.x; i < BV*FV; i += 256) {
        int b = i >> 8, f = i & 255;
        s += mask[(b*TV + t)*FV + f];
    }
    __shared__ float red[256];
    red[threadIdx.x] = s;
    __syncthreads();
    for (int st = 128; st > 0; st >>= 1) {
        if (threadIdx.x < st) red[threadIdx.x] += red[threadIdx.x + st];
        __syncthreads();
    }
    if (threadIdx.x == 0) g_msum[t] = red[0];
}

__global__ void final_k(float* __restrict__ out) {
    __shared__ float s[TV];
    int t = threadIdx.x;
    float acc = 0.f;
    for (int i = 0; i < NB2; i++) acc += g_lossPart[t*NB2 + i];
    s[t] = acc / (g_msum[t] + 1e-12f);
    __syncthreads();
    if (t == 0) {
        float L = 0.f;
        for (int i = 0; i < TV; i++) L += s[i];
        out[OFF_LOSS]     = L;
        out[OFF_LOSS + 1] = 0.f;
    }
}

// ---------------- launch ----------------
template<class KF, class... Args>
static inline void launch_pdl(KF kf, dim3 grid, dim3 block, Args... args) {
    cudaLaunchConfig_t cfg = {};
    cfg.gridDim = grid;
    cfg.blockDim = block;
    cfg.dynamicSmemBytes = 0;
    cfg.stream = 0;
    cudaLaunchAttribute at[1];
    at[0].id = cudaLaunchAttributeProgrammaticStreamSerialization;
    at[0].val.programmaticStreamSerializationAllowed = 1;
    cfg.attrs = at;
    cfg.numAttrs = 1;
    cudaLaunchKernelEx(&cfg, kf, args...);
}

extern "C" void kernel_launch(void* const* d_in, const int* in_sizes, int n_in,
                              void* d_out, int out_size) {
    const float* x      = (const float*)d_in[0];
    const float* mask   = (const float*)d_in[1];
    const float* deltas = (const float*)d_in[2];
    const float* h0     = (const float*)d_in[3];
    const float* Wdh    = (const float*)d_in[4];
    const float* bdh    = (const float*)d_in[5];
    const float* Wdx    = (const float*)d_in[6];
    const float* bdx    = (const float*)d_in[7];
    const float* Wh     = (const float*)d_in[8];
    const float* bh     = (const float*)d_in[9];
    const float* Wfr    = (const float*)d_in[10];
    const float* bfr    = (const float*)d_in[11];
    const float* Wwc    = (const float*)d_in[12];
    const float* bwc    = (const float*)d_in[13];
    const float* Wih    = (const float*)d_in[14];
    const float* bih    = (const float*)d_in[15];
    const float* Whh    = (const float*)d_in[16];
    const float* bhh    = (const float*)d_in[17];

    float* out      = (float*)d_out;
    float* ximp_out = out;
    float* rec_out  = out + OFF_REC;
    float* hfin     = out + OFF_HFIN;

    msum_k<<<TV, 256>>>(mask);

    // Pre-swizzle weights (B operands)
    swz_k<<<(3328*1024/2)/256, 256>>>(BOFF_G1, 3328, 1024, BL_G1{Wh, Whh});
    swz_k<<<(3072*512 /2)/256, 256>>>(BOFF_G3, 3072, 512,  BL_G3{Wih});
    swz_k<<<(256*256  /2)/256, 256>>>(BOFF_G2, 256,  256,  BL_G2{Wfr});
    swz_k<<<(1024*256 /2)/256, 256>>>(BOFF_P1, 1024, 256,  BL_P1{Wdh});
    swz_k<<<(256*512  /2)/256, 256>>>(BOFF_P2, 256,  512,  BL_P2{Wwc});

    // Pre-swizzle A operands for P1/P2 and G3 mask half
    swzA_P1_k<<<(32768*128)/256, 256>>>(deltas);
    swzA_P2_k<<<(32768*256)/256, 256>>>(deltas, mask, Wdx, bdx);
    swzA_G3m_k<<<(TV*BV*128)/256, 256>>>(mask);

    // P1: gammaH, M=32768, N=1024, K=256
    tgemm4_k<64,128,32,32><<<dim3(1024/128, 32768/64), 256>>>(
        FV, AOFF_P1, BOFF_P1, EP_P1{bdh});

    // h init (needs gammaH[0])
    hAinit_k<<<(BV*HV/2)/256, 256>>>(h0);

    // P2: beta, M=32768, N=256, K=512
    tgemm4_k<64,128,32,32><<<dim3(256/128, 32768/64), 256>>>(
        2*FV, AOFF_P2, BOFF_P2, EP_P2{bwc});

    for (int t = 0; t < TV; t++) {
        // G1: [x_h | gh], M=512, N=3328, K=1024 -> 208 blocks
        launch_pdl(tgemm4_k<64,128,32,32,EP_G1>, dim3(3328/128, 512/64), dim3(256),
                   HV, AOFF_G1, BOFF_G1, EP_G1{bh, bhh, x, mask, t});

        // G2: xu + combine/imputation/loss, 32 blocks
        launch_pdl(tgemm4_k<64,64,32,16,EP_G2>, dim3(256/64, 512/64), dim3(256),
                   FV, AOFF_G2, BOFF_G2, EP_G2{bfr, x, mask, rec_out, ximp_out, t});

        // G3+GRU fused: 3-gate GEMM + GRU update -> 128 blocks (one wave)
        launch_pdl(g3gru_k, dim3(HV/64, BV/64), dim3(256),
                   AOFF_G3 + t*AG3_STRIDE, bih, t,
                   (t == TV-1) ? hfin : (float*)nullptr);
    }

    final_k<<<1, TV>>>(out);
}